// round 1
// baseline (speedup 1.0000x reference)
#include <cuda_runtime.h>
#include <cuda_bf16.h>
#include <math.h>

// ---------------- problem constants ----------------
#define BATCH     4
#define SEQ       512
#define NTOK      (BATCH*SEQ)          // 2048
#define STATE     510
#define D_MODEL   1024
#define D_INNER   2048
#define D_STATE   128
#define NHEADS    32
#define HEADDIM   64
#define DCONV     4
#define CONV_DIM  (D_INNER + 2*D_STATE)            // 2304
#define D_IN_PROJ (2*D_INNER + 2*D_STATE + NHEADS) // 4384
#define NBLOCKS   4

// ---------------- scratch (device globals, no allocs) ----------------
__device__ float g_cat [NTOK * 512];
__device__ float g_tmp [NTOK * D_MODEL];
__device__ float g_h   [NTOK * D_MODEL];
__device__ float g_z   [NTOK * D_IN_PROJ];
__device__ float g_conv[NTOK * CONV_DIM];
__device__ float g_dt  [NTOK * NHEADS];
__device__ float g_dA  [NTOK * NHEADS];
__device__ float g_y   [NTOK * D_INNER];
__device__ float g_yn  [NTOK * D_INNER];

// ---------------- helpers ----------------
__device__ __forceinline__ float siluf(float v) { return v / (1.f + expf(-v)); }

__device__ __forceinline__ float blockReduceSum256(float v) {
    __shared__ float s[8];
    __shared__ float tot;
    int lane = threadIdx.x & 31, w = threadIdx.x >> 5;
    #pragma unroll
    for (int o = 16; o; o >>= 1) v += __shfl_xor_sync(0xffffffffu, v, o);
    if (lane == 0) s[w] = v;
    __syncthreads();
    if (threadIdx.x < 32) {
        float t = (threadIdx.x < 8) ? s[threadIdx.x] : 0.f;
        #pragma unroll
        for (int o = 4; o; o >>= 1) t += __shfl_xor_sync(0xffffffffu, t, o);
        if (threadIdx.x == 0) tot = t;
    }
    __syncthreads();
    return tot;
}

// ---------------- SGEMM 128x128x8, 256 threads, 8x8 microtile ----------------
// C[M,N] = A[M,K] @ B[K,N]  (+bias) (relu).  M % 128 == 0, K % 8 == 0; N guarded.
template<int BIAS, int RELU>
__global__ __launch_bounds__(256)
void sgemm128(const float* __restrict__ A, const float* __restrict__ B,
              const float* __restrict__ bias, float* __restrict__ C,
              int M, int N, int K)
{
    __shared__ float As[8][128];
    __shared__ float Bs[8][128];
    const int tid = threadIdx.x;
    const int m0 = blockIdx.y * 128;
    const int n0 = blockIdx.x * 128;

    const int arow = tid >> 1, acol = (tid & 1) << 2;
    const int brow = tid >> 5, bcol = (tid & 31) << 2;
    const int ty = tid >> 4, tx = tid & 15;

    float acc[8][8];
    #pragma unroll
    for (int i = 0; i < 8; i++)
        #pragma unroll
        for (int j = 0; j < 8; j++) acc[i][j] = 0.f;

    for (int k0 = 0; k0 < K; k0 += 8) {
        float4 av = *(const float4*)(A + (size_t)(m0 + arow) * K + k0 + acol);
        As[acol + 0][arow] = av.x;
        As[acol + 1][arow] = av.y;
        As[acol + 2][arow] = av.z;
        As[acol + 3][arow] = av.w;

        float4 bv = make_float4(0.f, 0.f, 0.f, 0.f);
        if (n0 + bcol < N)
            bv = *(const float4*)(B + (size_t)(k0 + brow) * N + n0 + bcol);
        *(float4*)&Bs[brow][bcol] = bv;

        __syncthreads();
        #pragma unroll
        for (int kk = 0; kk < 8; kk++) {
            float4 a0 = *(const float4*)&As[kk][ty * 8];
            float4 a1 = *(const float4*)&As[kk][ty * 8 + 4];
            float4 b0 = *(const float4*)&Bs[kk][tx * 8];
            float4 b1 = *(const float4*)&Bs[kk][tx * 8 + 4];
            float ar[8] = {a0.x, a0.y, a0.z, a0.w, a1.x, a1.y, a1.z, a1.w};
            float br[8] = {b0.x, b0.y, b0.z, b0.w, b1.x, b1.y, b1.z, b1.w};
            #pragma unroll
            for (int i = 0; i < 8; i++)
                #pragma unroll
                for (int j = 0; j < 8; j++)
                    acc[i][j] = fmaf(ar[i], br[j], acc[i][j]);
        }
        __syncthreads();
    }

    #pragma unroll
    for (int i = 0; i < 8; i++) {
        int row = m0 + ty * 8 + i;
        #pragma unroll
        for (int j = 0; j < 8; j++) {
            int col = n0 + tx * 8 + j;
            if (col < N) {
                float v = acc[i][j];
                if (BIAS) v += bias[col];
                if (RELU) v = fmaxf(v, 0.f);
                C[(size_t)row * N + col] = v;
            }
        }
    }
}

// ---------------- elementwise kernels ----------------
__global__ void concat_kernel(const float* __restrict__ x, const float* __restrict__ sl,
                              const float* __restrict__ cr, float* __restrict__ out)
{
    int idx = blockIdx.x * blockDim.x + threadIdx.x;   // NTOK*512
    int c = idx & 511, r = idx >> 9;
    float v;
    if (c < STATE)      v = x[(size_t)r * STATE + c];
    else if (c == STATE) v = sl[r];
    else                 v = cr[r];
    out[idx] = v;
}

__global__ void conv_silu_kernel(const float* __restrict__ zb, const float* __restrict__ cw,
                                 const float* __restrict__ cb, float* __restrict__ out)
{
    int idx = blockIdx.x * blockDim.x + threadIdx.x;   // NTOK*CONV_DIM
    if (idx >= NTOK * CONV_DIM) return;
    int ch = idx % CONV_DIM;
    int t  = idx / CONV_DIM;
    int l = t & (SEQ - 1), b = t >> 9;
    float s = cb[ch];
    #pragma unroll
    for (int k = 0; k < DCONV; k++) {
        int ll = l - (DCONV - 1) + k;
        if (ll >= 0)
            s = fmaf(zb[((size_t)(b * SEQ + ll)) * D_IN_PROJ + D_INNER + ch], cw[ch * DCONV + k], s);
    }
    out[idx] = siluf(s);
}

__global__ void dt_kernel(const float* __restrict__ zb, const float* __restrict__ dtb,
                          const float* __restrict__ Alog,
                          float* __restrict__ dt, float* __restrict__ dA)
{
    int idx = blockIdx.x * blockDim.x + threadIdx.x;   // NTOK*NHEADS
    if (idx >= NTOK * NHEADS) return;
    int hh = idx & (NHEADS - 1), row = idx >> 5;
    float v = zb[(size_t)row * D_IN_PROJ + (D_INNER + CONV_DIM) + hh] + dtb[hh];
    float sp = (v > 20.f) ? v : log1pf(expf(v));
    float a = -expf(Alog[hh]);
    dt[idx] = sp;
    dA[idx] = expf(sp * a);
}

// ---------------- selective scan: 1 CTA per (b, head) ----------------
// 256 threads: p = tid>>2 (0..63), nq = tid&3 (n-quarter, 32 states each).
__global__ __launch_bounds__(256)
void scan_kernel(const float* __restrict__ conv, const float* __restrict__ dt,
                 const float* __restrict__ dA, const float* __restrict__ Dsk,
                 float* __restrict__ y)
{
    int bh = blockIdx.x;
    int b = bh >> 5, hh = bh & 31;
    int tid = threadIdx.x;
    int p = tid >> 2, nq = tid & 3;

    float hs[32];
    #pragma unroll
    for (int i = 0; i < 32; i++) hs[i] = 0.f;
    float dsk = Dsk[hh];
    const size_t convb = (size_t)b * SEQ * CONV_DIM;

    for (int l = 0; l < SEQ; l++) {
        const float* row = conv + convb + (size_t)l * CONV_DIM;
        int tix = (b * SEQ + l) * NHEADS + hh;
        float dtv = dt[tix];
        float dav = dA[tix];
        float xp = row[hh * HEADDIM + p];
        float coef = dtv * xp;
        const float4* B4 = (const float4*)(row + D_INNER);
        const float4* C4 = (const float4*)(row + D_INNER + D_STATE);
        float acc = 0.f;
        #pragma unroll
        for (int i = 0; i < 8; i++) {
            float4 bv = B4[nq * 8 + i];
            float4 cv = C4[nq * 8 + i];
            int j = i * 4;
            hs[j    ] = fmaf(hs[j    ], dav, coef * bv.x); acc = fmaf(hs[j    ], cv.x, acc);
            hs[j + 1] = fmaf(hs[j + 1], dav, coef * bv.y); acc = fmaf(hs[j + 1], cv.y, acc);
            hs[j + 2] = fmaf(hs[j + 2], dav, coef * bv.z); acc = fmaf(hs[j + 2], cv.z, acc);
            hs[j + 3] = fmaf(hs[j + 3], dav, coef * bv.w); acc = fmaf(hs[j + 3], cv.w, acc);
        }
        acc += __shfl_xor_sync(0xffffffffu, acc, 1);
        acc += __shfl_xor_sync(0xffffffffu, acc, 2);
        if (nq == 0)
            y[((size_t)(b * SEQ + l)) * D_INNER + hh * HEADDIM + p] = acc + dsk * xp;
    }
}

// ---------------- gated RMSNorm ----------------
__global__ __launch_bounds__(256)
void gated_norm_kernel(const float* __restrict__ y, const float* __restrict__ z,
                       const float* __restrict__ nw, float* __restrict__ out)
{
    int r = blockIdx.x;   // token row
    float g[8];
    float ss = 0.f;
    #pragma unroll
    for (int j = 0; j < 8; j++) {
        int c = j * 256 + threadIdx.x;
        float zv = z[(size_t)r * D_IN_PROJ + c];
        float gv = y[(size_t)r * D_INNER + c] * siluf(zv);
        g[j] = gv;
        ss = fmaf(gv, gv, ss);
    }
    ss = blockReduceSum256(ss);
    float inv = rsqrtf(ss / (float)D_INNER + 1e-5f);
    #pragma unroll
    for (int j = 0; j < 8; j++) {
        int c = j * 256 + threadIdx.x;
        out[(size_t)r * D_INNER + c] = g[j] * inv * nw[c];
    }
}

// ---------------- final N=1 projection ----------------
__global__ __launch_bounds__(256)
void dot_kernel(const float* __restrict__ t, const float* __restrict__ w,
                const float* __restrict__ b, float* __restrict__ out)
{
    int r = blockIdx.x;
    float s = 0.f;
    for (int k = threadIdx.x; k < D_MODEL; k += 256)
        s = fmaf(t[(size_t)r * D_MODEL + k], w[k], s);
    s = blockReduceSum256(s);
    if (threadIdx.x == 0) out[r] = s + b[0];
}

// ---------------- launch ----------------
extern "C" void kernel_launch(void* const* d_in, const int* in_sizes, int n_in,
                              void* d_out, int out_size)
{
    const float* x    = (const float*)d_in[0];
    const float* sl   = (const float*)d_in[1];
    const float* cr   = (const float*)d_in[2];
    const float* iw1  = (const float*)d_in[3];
    const float* ib1  = (const float*)d_in[4];
    const float* iw2  = (const float*)d_in[5];
    const float* ib2  = (const float*)d_in[6];
    const float* Win  = (const float*)d_in[7];
    const float* cw   = (const float*)d_in[8];
    const float* cb   = (const float*)d_in[9];
    const float* dtb  = (const float*)d_in[10];
    const float* Alog = (const float*)d_in[11];
    const float* Dsk  = (const float*)d_in[12];
    const float* nw   = (const float*)d_in[13];
    const float* Wout = (const float*)d_in[14];
    const float* ow1  = (const float*)d_in[15];
    const float* ob1  = (const float*)d_in[16];
    const float* ow2  = (const float*)d_in[17];
    const float* ob2  = (const float*)d_in[18];
    float* out = (float*)d_out;

    float *cat, *tmp, *h, *z, *conv, *dt, *dA, *y, *yn;
    cudaGetSymbolAddress((void**)&cat,  g_cat);
    cudaGetSymbolAddress((void**)&tmp,  g_tmp);
    cudaGetSymbolAddress((void**)&h,    g_h);
    cudaGetSymbolAddress((void**)&z,    g_z);
    cudaGetSymbolAddress((void**)&conv, g_conv);
    cudaGetSymbolAddress((void**)&dt,   g_dt);
    cudaGetSymbolAddress((void**)&dA,   g_dA);
    cudaGetSymbolAddress((void**)&y,    g_y);
    cudaGetSymbolAddress((void**)&yn,   g_yn);

    const int MT = NTOK / 128;   // 16 M-tiles

    // input MLP
    concat_kernel<<<NTOK * 512 / 256, 256>>>(x, sl, cr, cat);
    sgemm128<1, 1><<<dim3(512 / 128, MT), 256>>>(cat, iw1, ib1, tmp, NTOK, 512, 512);
    sgemm128<1, 0><<<dim3(D_MODEL / 128, MT), 256>>>(tmp, iw2, ib2, h, NTOK, D_MODEL, 512);

    for (int i = 0; i < NBLOCKS; i++) {
        sgemm128<0, 0><<<dim3((D_IN_PROJ + 127) / 128, MT), 256>>>(
            h, Win + (size_t)i * D_MODEL * D_IN_PROJ, nullptr, z, NTOK, D_IN_PROJ, D_MODEL);
        conv_silu_kernel<<<(NTOK * CONV_DIM + 255) / 256, 256>>>(
            z, cw + (size_t)i * CONV_DIM * DCONV, cb + (size_t)i * CONV_DIM, conv);
        dt_kernel<<<(NTOK * NHEADS) / 256, 256>>>(
            z, dtb + i * NHEADS, Alog + i * NHEADS, dt, dA);
        scan_kernel<<<BATCH * NHEADS, 256>>>(conv, dt, dA, Dsk + i * NHEADS, y);
        gated_norm_kernel<<<NTOK, 256>>>(y, z, nw + (size_t)i * D_INNER, yn);
        sgemm128<0, 0><<<dim3(D_MODEL / 128, MT), 256>>>(
            yn, Wout + (size_t)i * D_INNER * D_MODEL, nullptr, h, NTOK, D_MODEL, D_INNER);
    }

    // output MLP
    sgemm128<1, 1><<<dim3(D_MODEL / 128, MT), 256>>>(h, ow1, ob1, tmp, NTOK, D_MODEL, D_MODEL);
    dot_kernel<<<NTOK, 256>>>(tmp, ow2, ob2, out);
}

// round 5
// speedup vs baseline: 1.4044x; 1.4044x over previous
#include <cuda_runtime.h>
#include <cuda.h>
#include <cuda_bf16.h>
#include <math.h>
#include <stdint.h>

// ---------------- problem constants ----------------
#define BATCH     4
#define SEQ       512
#define NTOK      (BATCH*SEQ)          // 2048
#define STATE     510
#define D_MODEL   1024
#define D_INNER   2048
#define D_STATE   128
#define NHEADS    32
#define HEADDIM   64
#define DCONV     4
#define CONV_DIM  (D_INNER + 2*D_STATE)            // 2304
#define D_IN_PROJ (2*D_INNER + 2*D_STATE + NHEADS) // 4384
#define NBLOCKS   4

// ---------------- scratch (device globals, no allocs) ----------------
__device__ float g_cat [NTOK * 512];
__device__ float g_tmp [NTOK * D_MODEL];
__device__ float g_h   [NTOK * D_MODEL];
__device__ float g_z   [NTOK * D_IN_PROJ];
__device__ float g_conv[NTOK * CONV_DIM];
__device__ float g_dt  [NTOK * NHEADS];
__device__ float g_dA  [NTOK * NHEADS];
__device__ float g_y   [NTOK * D_INNER];
__device__ float g_yn  [NTOK * D_INNER];

// ================= helpers =================
__device__ __forceinline__ uint32_t smem_to_u32(const void* p) {
    uint32_t a;
    asm("{ .reg .u64 t; cvta.to.shared.u64 t, %1; cvt.u32.u64 %0, t; }" : "=r"(a) : "l"(p));
    return a;
}
#define CP_ASYNC16(dst, src) \
    asm volatile("cp.async.ca.shared.global [%0], [%1], 16;" :: "r"(dst), "l"(src) : "memory")
#define CP_COMMIT() asm volatile("cp.async.commit_group;" ::: "memory")
#define CP_WAIT1()  asm volatile("cp.async.wait_group 1;" ::: "memory")
#define CP_WAIT0()  asm volatile("cp.async.wait_group 0;" ::: "memory")

__device__ __forceinline__ void tf32split(float x, uint32_t& hi, uint32_t& lo) {
    uint32_t h;
    asm("cvt.rna.tf32.f32 %0, %1;" : "=r"(h) : "f"(x));
    hi = h;
    lo = __float_as_uint(x - __uint_as_float(h));
}

#define MMA_TF32(cr, a, b) \
    asm volatile("mma.sync.aligned.m16n8k8.row.col.f32.tf32.tf32.f32 " \
        "{%0,%1,%2,%3},{%4,%5,%6,%7},{%8,%9},{%0,%1,%2,%3};" \
        : "+f"((cr)[0]), "+f"((cr)[1]), "+f"((cr)[2]), "+f"((cr)[3]) \
        : "r"((a)[0]), "r"((a)[1]), "r"((a)[2]), "r"((a)[3]), \
          "r"((b)[0]), "r"((b)[1]))

// ================= TF32 tensor-core GEMM (3xTF32 compensated) =================
// C[M,N] = A[M,K] @ B[K,N] (+bias)(relu). CTA tile 128x128, K-chunk 32,
// cp.async double-buffered. 8 warps, warp tile 64x32 (m16n8k8 atoms).
// Smem per buffer: A[128][36] floats (4608) + B[32][136] floats (4352) = 8960 floats.
#define GEMM_SMEM_FLOATS (2 * 8960)
#define GEMM_SMEM_BYTES  (GEMM_SMEM_FLOATS * 4)

template<int BIAS, int RELU>
__global__ __launch_bounds__(256)
void mma_gemm(const float* __restrict__ A, const float* __restrict__ B,
              const float* __restrict__ bias, float* __restrict__ C,
              int M, int N, int K)
{
    extern __shared__ float sm[];
    const uint32_t sbase = smem_to_u32(sm);

    const int tid = threadIdx.x, lane = tid & 31, w = tid >> 5;
    const int wm = w >> 2, wn = w & 3;          // warp grid 2(m) x 4(n)
    const int grp = lane >> 2, kq = lane & 3;
    const int m0 = blockIdx.y * 128, n0 = blockIdx.x * 128;

    // ldg->sts index precompute
    const int ar = tid >> 1, ah = tid & 1;      // A: row, k-half
    const int bk = tid >> 3, bf = tid & 7;      // B: k-row, f4 subgroup

    float c[4][4][4];
    #pragma unroll
    for (int i = 0; i < 4; i++)
        #pragma unroll
        for (int j = 0; j < 4; j++)
            #pragma unroll
            for (int q = 0; q < 4; q++) c[i][j][q] = 0.f;

    const int nch = K >> 5;

    // ---- async chunk issue ----
    auto issue = [&](int ch) {
        const uint32_t boff = (uint32_t)(ch & 1) * (8960u * 4u);
        const int k0 = ch << 5;
        // A tile: [128 rows][32 k] -> sm A[row][k], row stride 36 floats
        const float* asrc = A + (size_t)(m0 + ar) * K + k0 + ah * 16;
        uint32_t adst = sbase + boff + (uint32_t)(ar * 36 + ah * 16) * 4u;
        #pragma unroll
        for (int i = 0; i < 4; i++)
            CP_ASYNC16(adst + i * 16u, asrc + i * 4);
        // B tile: [32 k][128 n] -> sm B[k][n], row stride 136 floats
        #pragma unroll
        for (int i = 0; i < 4; i++) {
            int nf = bf + i * 8;
            int ncol = n0 + nf * 4;
            const float* bsrc = B + (size_t)(k0 + bk) * N + (ncol < N ? ncol : 0);
            uint32_t bdst = sbase + boff + (4608u + (uint32_t)(bk * 136 + nf * 4)) * 4u;
            CP_ASYNC16(bdst, bsrc);
        }
        CP_COMMIT();
    };

    issue(0);

    for (int ch = 0; ch < nch; ch++) {
        if (ch + 1 < nch) { issue(ch + 1); CP_WAIT1(); }
        else              { CP_WAIT0(); }
        __syncthreads();

        const float* Af = sm + (ch & 1) * 8960;
        const float* Bf = Af + 4608;

        #pragma unroll
        for (int kk = 0; kk < 4; kk++) {
            const int kb = kk * 8;
            uint32_t ahi[4][4], alo[4][4];
            #pragma unroll
            for (int ma = 0; ma < 4; ma++) {
                int r0 = wm * 64 + ma * 16 + grp;
                float x0 = Af[r0 * 36 + kb + kq];
                float x1 = Af[(r0 + 8) * 36 + kb + kq];
                float x2 = Af[r0 * 36 + kb + kq + 4];
                float x3 = Af[(r0 + 8) * 36 + kb + kq + 4];
                tf32split(x0, ahi[ma][0], alo[ma][0]);
                tf32split(x1, ahi[ma][1], alo[ma][1]);
                tf32split(x2, ahi[ma][2], alo[ma][2]);
                tf32split(x3, ahi[ma][3], alo[ma][3]);
            }
            uint32_t bhi[4][2], blo[4][2];
            #pragma unroll
            for (int na = 0; na < 4; na++) {
                int col = wn * 32 + na * 8 + grp;
                float y0 = Bf[(kb + kq) * 136 + col];
                float y1 = Bf[(kb + kq + 4) * 136 + col];
                tf32split(y0, bhi[na][0], blo[na][0]);
                tf32split(y1, bhi[na][1], blo[na][1]);
            }
            #pragma unroll
            for (int ma = 0; ma < 4; ma++)
                #pragma unroll
                for (int na = 0; na < 4; na++) {
                    MMA_TF32(c[ma][na], ahi[ma], bhi[na]);
                    MMA_TF32(c[ma][na], ahi[ma], blo[na]);
                    MMA_TF32(c[ma][na], alo[ma], bhi[na]);
                }
        }
        __syncthreads();
    }

    // ---- epilogue ----
    #pragma unroll
    for (int ma = 0; ma < 4; ma++) {
        int row = m0 + wm * 64 + ma * 16 + grp;
        #pragma unroll
        for (int na = 0; na < 4; na++) {
            int col = n0 + wn * 32 + na * 8 + kq * 2;
            if (col < N) {
                float b0 = 0.f, b1 = 0.f;
                if (BIAS) { b0 = bias[col]; b1 = bias[col + 1]; }
                float v0 = c[ma][na][0] + b0, v1 = c[ma][na][1] + b1;
                float v2 = c[ma][na][2] + b0, v3 = c[ma][na][3] + b1;
                if (RELU) {
                    v0 = fmaxf(v0, 0.f); v1 = fmaxf(v1, 0.f);
                    v2 = fmaxf(v2, 0.f); v3 = fmaxf(v3, 0.f);
                }
                *(float2*)(C + (size_t)row * N + col)       = make_float2(v0, v1);
                *(float2*)(C + (size_t)(row + 8) * N + col) = make_float2(v2, v3);
            }
        }
    }
}

// ---------------- helpers ----------------
__device__ __forceinline__ float siluf(float v) { return v / (1.f + expf(-v)); }

__device__ __forceinline__ float blockReduceSum256(float v) {
    __shared__ float s[8];
    __shared__ float tot;
    int lane = threadIdx.x & 31, w = threadIdx.x >> 5;
    #pragma unroll
    for (int o = 16; o; o >>= 1) v += __shfl_xor_sync(0xffffffffu, v, o);
    if (lane == 0) s[w] = v;
    __syncthreads();
    if (threadIdx.x < 32) {
        float t = (threadIdx.x < 8) ? s[threadIdx.x] : 0.f;
        #pragma unroll
        for (int o = 4; o; o >>= 1) t += __shfl_xor_sync(0xffffffffu, t, o);
        if (threadIdx.x == 0) tot = t;
    }
    __syncthreads();
    return tot;
}

// ---------------- elementwise kernels ----------------
__global__ void concat_kernel(const float* __restrict__ x, const float* __restrict__ sl,
                              const float* __restrict__ cr, float* __restrict__ out)
{
    int idx = blockIdx.x * blockDim.x + threadIdx.x;   // NTOK*512
    int c = idx & 511, r = idx >> 9;
    float v;
    if (c < STATE)      v = x[(size_t)r * STATE + c];
    else if (c == STATE) v = sl[r];
    else                 v = cr[r];
    out[idx] = v;
}

__global__ void conv_silu_kernel(const float* __restrict__ zb, const float* __restrict__ cw,
                                 const float* __restrict__ cb, float* __restrict__ out)
{
    int idx = blockIdx.x * blockDim.x + threadIdx.x;   // NTOK*CONV_DIM
    if (idx >= NTOK * CONV_DIM) return;
    int ch = idx % CONV_DIM;
    int t  = idx / CONV_DIM;
    int l = t & (SEQ - 1), b = t >> 9;
    float s = cb[ch];
    #pragma unroll
    for (int k = 0; k < DCONV; k++) {
        int ll = l - (DCONV - 1) + k;
        if (ll >= 0)
            s = fmaf(zb[((size_t)(b * SEQ + ll)) * D_IN_PROJ + D_INNER + ch], cw[ch * DCONV + k], s);
    }
    out[idx] = siluf(s);
}

__global__ void dt_kernel(const float* __restrict__ zb, const float* __restrict__ dtb,
                          const float* __restrict__ Alog,
                          float* __restrict__ dt, float* __restrict__ dA)
{
    int idx = blockIdx.x * blockDim.x + threadIdx.x;   // NTOK*NHEADS
    if (idx >= NTOK * NHEADS) return;
    int hh = idx & (NHEADS - 1), row = idx >> 5;
    float v = zb[(size_t)row * D_IN_PROJ + (D_INNER + CONV_DIM) + hh] + dtb[hh];
    float sp = (v > 20.f) ? v : log1pf(expf(v));
    float a = -expf(Alog[hh]);
    dt[idx] = sp;
    dA[idx] = expf(sp * a);
}

// ---------------- selective scan: 1 CTA per (b, head) ----------------
__global__ __launch_bounds__(256)
void scan_kernel(const float* __restrict__ conv, const float* __restrict__ dt,
                 const float* __restrict__ dA, const float* __restrict__ Dsk,
                 float* __restrict__ y)
{
    int bh = blockIdx.x;
    int b = bh >> 5, hh = bh & 31;
    int tid = threadIdx.x;
    int p = tid >> 2, nq = tid & 3;

    float hs[32];
    #pragma unroll
    for (int i = 0; i < 32; i++) hs[i] = 0.f;
    float dsk = Dsk[hh];
    const size_t convb = (size_t)b * SEQ * CONV_DIM;

    for (int l = 0; l < SEQ; l++) {
        const float* row = conv + convb + (size_t)l * CONV_DIM;
        int tix = (b * SEQ + l) * NHEADS + hh;
        float dtv = dt[tix];
        float dav = dA[tix];
        float xp = row[hh * HEADDIM + p];
        float coef = dtv * xp;
        const float4* B4 = (const float4*)(row + D_INNER);
        const float4* C4 = (const float4*)(row + D_INNER + D_STATE);
        float acc = 0.f;
        #pragma unroll
        for (int i = 0; i < 8; i++) {
            float4 bv = B4[nq * 8 + i];
            float4 cv = C4[nq * 8 + i];
            int j = i * 4;
            hs[j    ] = fmaf(hs[j    ], dav, coef * bv.x); acc = fmaf(hs[j    ], cv.x, acc);
            hs[j + 1] = fmaf(hs[j + 1], dav, coef * bv.y); acc = fmaf(hs[j + 1], cv.y, acc);
            hs[j + 2] = fmaf(hs[j + 2], dav, coef * bv.z); acc = fmaf(hs[j + 2], cv.z, acc);
            hs[j + 3] = fmaf(hs[j + 3], dav, coef * bv.w); acc = fmaf(hs[j + 3], cv.w, acc);
        }
        acc += __shfl_xor_sync(0xffffffffu, acc, 1);
        acc += __shfl_xor_sync(0xffffffffu, acc, 2);
        if (nq == 0)
            y[((size_t)(b * SEQ + l)) * D_INNER + hh * HEADDIM + p] = acc + dsk * xp;
    }
}

// ---------------- gated RMSNorm ----------------
__global__ __launch_bounds__(256)
void gated_norm_kernel(const float* __restrict__ y, const float* __restrict__ z,
                       const float* __restrict__ nw, float* __restrict__ out)
{
    int r = blockIdx.x;
    float g[8];
    float ss = 0.f;
    #pragma unroll
    for (int j = 0; j < 8; j++) {
        int c = j * 256 + threadIdx.x;
        float zv = z[(size_t)r * D_IN_PROJ + c];
        float gv = y[(size_t)r * D_INNER + c] * siluf(zv);
        g[j] = gv;
        ss = fmaf(gv, gv, ss);
    }
    ss = blockReduceSum256(ss);
    float inv = rsqrtf(ss / (float)D_INNER + 1e-5f);
    #pragma unroll
    for (int j = 0; j < 8; j++) {
        int c = j * 256 + threadIdx.x;
        out[(size_t)r * D_INNER + c] = g[j] * inv * nw[c];
    }
}

// ---------------- final N=1 projection ----------------
__global__ __launch_bounds__(256)
void dot_kernel(const float* __restrict__ t, const float* __restrict__ w,
                const float* __restrict__ b, float* __restrict__ out)
{
    int r = blockIdx.x;
    float s = 0.f;
    for (int k = threadIdx.x; k < D_MODEL; k += 256)
        s = fmaf(t[(size_t)r * D_MODEL + k], w[k], s);
    s = blockReduceSum256(s);
    if (threadIdx.x == 0) out[r] = s + b[0];
}

// ---------------- launch ----------------
extern "C" void kernel_launch(void* const* d_in, const int* in_sizes, int n_in,
                              void* d_out, int out_size)
{
    const float* x    = (const float*)d_in[0];
    const float* sl   = (const float*)d_in[1];
    const float* cr   = (const float*)d_in[2];
    const float* iw1  = (const float*)d_in[3];
    const float* ib1  = (const float*)d_in[4];
    const float* iw2  = (const float*)d_in[5];
    const float* ib2  = (const float*)d_in[6];
    const float* Win  = (const float*)d_in[7];
    const float* cw   = (const float*)d_in[8];
    const float* cb   = (const float*)d_in[9];
    const float* dtb  = (const float*)d_in[10];
    const float* Alog = (const float*)d_in[11];
    const float* Dsk  = (const float*)d_in[12];
    const float* nw   = (const float*)d_in[13];
    const float* Wout = (const float*)d_in[14];
    const float* ow1  = (const float*)d_in[15];
    const float* ob1  = (const float*)d_in[16];
    const float* ow2  = (const float*)d_in[17];
    const float* ob2  = (const float*)d_in[18];
    float* out = (float*)d_out;

    float *cat, *tmp, *h, *z, *conv, *dt, *dA, *y, *yn;
    cudaGetSymbolAddress((void**)&cat,  g_cat);
    cudaGetSymbolAddress((void**)&tmp,  g_tmp);
    cudaGetSymbolAddress((void**)&h,    g_h);
    cudaGetSymbolAddress((void**)&z,    g_z);
    cudaGetSymbolAddress((void**)&conv, g_conv);
    cudaGetSymbolAddress((void**)&dt,   g_dt);
    cudaGetSymbolAddress((void**)&dA,   g_dA);
    cudaGetSymbolAddress((void**)&y,    g_y);
    cudaGetSymbolAddress((void**)&yn,   g_yn);

    cudaFuncSetAttribute(mma_gemm<1,1>, cudaFuncAttributeMaxDynamicSharedMemorySize, GEMM_SMEM_BYTES);
    cudaFuncSetAttribute(mma_gemm<1,0>, cudaFuncAttributeMaxDynamicSharedMemorySize, GEMM_SMEM_BYTES);
    cudaFuncSetAttribute(mma_gemm<0,0>, cudaFuncAttributeMaxDynamicSharedMemorySize, GEMM_SMEM_BYTES);

    const int MT = NTOK / 128;   // 16 M-tiles

    // input MLP
    concat_kernel<<<NTOK * 512 / 256, 256>>>(x, sl, cr, cat);
    mma_gemm<1,1><<<dim3(512/128, MT), 256, GEMM_SMEM_BYTES>>>(cat, iw1, ib1, tmp, NTOK, 512, 512);
    mma_gemm<1,0><<<dim3(D_MODEL/128, MT), 256, GEMM_SMEM_BYTES>>>(tmp, iw2, ib2, h, NTOK, D_MODEL, 512);

    for (int i = 0; i < NBLOCKS; i++) {
        mma_gemm<0,0><<<dim3((D_IN_PROJ + 127)/128, MT), 256, GEMM_SMEM_BYTES>>>(
            h, Win + (size_t)i * D_MODEL * D_IN_PROJ, nullptr, z, NTOK, D_IN_PROJ, D_MODEL);
        conv_silu_kernel<<<(NTOK * CONV_DIM + 255) / 256, 256>>>(
            z, cw + (size_t)i * CONV_DIM * DCONV, cb + (size_t)i * CONV_DIM, conv);
        dt_kernel<<<(NTOK * NHEADS) / 256, 256>>>(
            z, dtb + i * NHEADS, Alog + i * NHEADS, dt, dA);
        scan_kernel<<<BATCH * NHEADS, 256>>>(conv, dt, dA, Dsk + i * NHEADS, y);
        gated_norm_kernel<<<NTOK, 256>>>(y, z, nw + (size_t)i * D_INNER, yn);
        mma_gemm<0,0><<<dim3(D_MODEL/128, MT), 256, GEMM_SMEM_BYTES>>>(
            yn, Wout + (size_t)i * D_INNER * D_MODEL, nullptr, h, NTOK, D_MODEL, D_INNER);
    }

    // output MLP
    mma_gemm<1,1><<<dim3(D_MODEL/128, MT), 256, GEMM_SMEM_BYTES>>>(h, ow1, ob1, tmp, NTOK, D_MODEL, D_MODEL);
    dot_kernel<<<NTOK, 256>>>(tmp, ow2, ob2, out);
}

// round 7
// speedup vs baseline: 1.4746x; 1.0500x over previous
#include <cuda_runtime.h>
#include <cuda.h>
#include <cuda_bf16.h>
#include <math.h>
#include <stdint.h>

// ---------------- problem constants ----------------
#define BATCH     4
#define SEQ       512
#define NTOK      (BATCH*SEQ)          // 2048
#define STATE     510
#define D_MODEL   1024
#define D_INNER   2048
#define D_STATE   128
#define NHEADS    32
#define HEADDIM   64
#define DCONV     4
#define CONV_DIM  (D_INNER + 2*D_STATE)            // 2304
#define D_IN_PROJ (2*D_INNER + 2*D_STATE + NHEADS) // 4384
#define NBLOCKS   4

// ---------------- scratch (device globals, no allocs) ----------------
__device__ float g_cat [NTOK * 512];
__device__ float g_tmp [NTOK * D_MODEL];
__device__ float g_h   [NTOK * D_MODEL];
__device__ float g_z   [NTOK * D_IN_PROJ];
__device__ float g_conv[NTOK * CONV_DIM];
__device__ float g_dt  [NTOK * NHEADS];
__device__ float g_dA  [NTOK * NHEADS];
__device__ float g_y   [NTOK * D_INNER];
__device__ float g_yn  [NTOK * D_INNER];

// ================= helpers =================
__device__ __forceinline__ uint32_t smem_to_u32(const void* p) {
    uint32_t a;
    asm("{ .reg .u64 t; cvta.to.shared.u64 t, %1; cvt.u32.u64 %0, t; }" : "=r"(a) : "l"(p));
    return a;
}
#define CP_ASYNC16(dst, src) \
    asm volatile("cp.async.ca.shared.global [%0], [%1], 16;" :: "r"(dst), "l"(src) : "memory")
#define CP_COMMIT() asm volatile("cp.async.commit_group;" ::: "memory")
#define CP_WAIT1()  asm volatile("cp.async.wait_group 1;" ::: "memory")
#define CP_WAIT0()  asm volatile("cp.async.wait_group 0;" ::: "memory")

__device__ __forceinline__ void tf32split(float x, uint32_t& hi, uint32_t& lo) {
    uint32_t h;
    asm("cvt.rna.tf32.f32 %0, %1;" : "=r"(h) : "f"(x));
    hi = h;
    lo = __float_as_uint(x - __uint_as_float(h));
}

#define MMA_TF32(cr, a, b) \
    asm volatile("mma.sync.aligned.m16n8k8.row.col.f32.tf32.tf32.f32 " \
        "{%0,%1,%2,%3},{%4,%5,%6,%7},{%8,%9},{%0,%1,%2,%3};" \
        : "+f"((cr)[0]), "+f"((cr)[1]), "+f"((cr)[2]), "+f"((cr)[3]) \
        : "r"((a)[0]), "r"((a)[1]), "r"((a)[2]), "r"((a)[3]), \
          "r"((b)[0]), "r"((b)[1]))

// ================= TF32 tensor-core GEMM (3xTF32 compensated) =================
#define GEMM_SMEM_FLOATS (2 * 8960)
#define GEMM_SMEM_BYTES  (GEMM_SMEM_FLOATS * 4)

template<int BIAS, int RELU>
__global__ __launch_bounds__(256)
void mma_gemm(const float* __restrict__ A, const float* __restrict__ B,
              const float* __restrict__ bias, float* __restrict__ C,
              int M, int N, int K)
{
    extern __shared__ float sm[];
    const uint32_t sbase = smem_to_u32(sm);

    const int tid = threadIdx.x, lane = tid & 31, w = tid >> 5;
    const int wm = w >> 2, wn = w & 3;          // warp grid 2(m) x 4(n)
    const int grp = lane >> 2, kq = lane & 3;
    const int m0 = blockIdx.y * 128, n0 = blockIdx.x * 128;

    const int ar = tid >> 1, ah = tid & 1;      // A: row, k-half
    const int bk = tid >> 3, bf = tid & 7;      // B: k-row, f4 subgroup

    float c[4][4][4];
    #pragma unroll
    for (int i = 0; i < 4; i++)
        #pragma unroll
        for (int j = 0; j < 4; j++)
            #pragma unroll
            for (int q = 0; q < 4; q++) c[i][j][q] = 0.f;

    const int nch = K >> 5;

    auto issue = [&](int ch) {
        const uint32_t boff = (uint32_t)(ch & 1) * (8960u * 4u);
        const int k0 = ch << 5;
        const float* asrc = A + (size_t)(m0 + ar) * K + k0 + ah * 16;
        uint32_t adst = sbase + boff + (uint32_t)(ar * 36 + ah * 16) * 4u;
        #pragma unroll
        for (int i = 0; i < 4; i++)
            CP_ASYNC16(adst + i * 16u, asrc + i * 4);
        #pragma unroll
        for (int i = 0; i < 4; i++) {
            int nf = bf + i * 8;
            int ncol = n0 + nf * 4;
            const float* bsrc = B + (size_t)(k0 + bk) * N + (ncol < N ? ncol : 0);
            uint32_t bdst = sbase + boff + (4608u + (uint32_t)(bk * 136 + nf * 4)) * 4u;
            CP_ASYNC16(bdst, bsrc);
        }
        CP_COMMIT();
    };

    issue(0);

    for (int ch = 0; ch < nch; ch++) {
        if (ch + 1 < nch) { issue(ch + 1); CP_WAIT1(); }
        else              { CP_WAIT0(); }
        __syncthreads();

        const float* Af = sm + (ch & 1) * 8960;
        const float* Bf = Af + 4608;

        #pragma unroll
        for (int kk = 0; kk < 4; kk++) {
            const int kb = kk * 8;
            uint32_t ahi[4][4], alo[4][4];
            #pragma unroll
            for (int ma = 0; ma < 4; ma++) {
                int r0 = wm * 64 + ma * 16 + grp;
                float x0 = Af[r0 * 36 + kb + kq];
                float x1 = Af[(r0 + 8) * 36 + kb + kq];
                float x2 = Af[r0 * 36 + kb + kq + 4];
                float x3 = Af[(r0 + 8) * 36 + kb + kq + 4];
                tf32split(x0, ahi[ma][0], alo[ma][0]);
                tf32split(x1, ahi[ma][1], alo[ma][1]);
                tf32split(x2, ahi[ma][2], alo[ma][2]);
                tf32split(x3, ahi[ma][3], alo[ma][3]);
            }
            uint32_t bhi[4][2], blo[4][2];
            #pragma unroll
            for (int na = 0; na < 4; na++) {
                int col = wn * 32 + na * 8 + grp;
                float y0 = Bf[(kb + kq) * 136 + col];
                float y1 = Bf[(kb + kq + 4) * 136 + col];
                tf32split(y0, bhi[na][0], blo[na][0]);
                tf32split(y1, bhi[na][1], blo[na][1]);
            }
            #pragma unroll
            for (int ma = 0; ma < 4; ma++)
                #pragma unroll
                for (int na = 0; na < 4; na++) {
                    MMA_TF32(c[ma][na], ahi[ma], bhi[na]);
                    MMA_TF32(c[ma][na], ahi[ma], blo[na]);
                    MMA_TF32(c[ma][na], alo[ma], bhi[na]);
                }
        }
        __syncthreads();
    }

    #pragma unroll
    for (int ma = 0; ma < 4; ma++) {
        int row = m0 + wm * 64 + ma * 16 + grp;
        #pragma unroll
        for (int na = 0; na < 4; na++) {
            int col = n0 + wn * 32 + na * 8 + kq * 2;
            if (col < N) {
                float b0 = 0.f, b1 = 0.f;
                if (BIAS) { b0 = bias[col]; b1 = bias[col + 1]; }
                float v0 = c[ma][na][0] + b0, v1 = c[ma][na][1] + b1;
                float v2 = c[ma][na][2] + b0, v3 = c[ma][na][3] + b1;
                if (RELU) {
                    v0 = fmaxf(v0, 0.f); v1 = fmaxf(v1, 0.f);
                    v2 = fmaxf(v2, 0.f); v3 = fmaxf(v3, 0.f);
                }
                *(float2*)(C + (size_t)row * N + col)       = make_float2(v0, v1);
                *(float2*)(C + (size_t)(row + 8) * N + col) = make_float2(v2, v3);
            }
        }
    }
}

// ---------------- helpers ----------------
__device__ __forceinline__ float siluf(float v) { return v / (1.f + expf(-v)); }

__device__ __forceinline__ float blockReduceSum256(float v) {
    __shared__ float s[8];
    __shared__ float tot;
    int lane = threadIdx.x & 31, w = threadIdx.x >> 5;
    #pragma unroll
    for (int o = 16; o; o >>= 1) v += __shfl_xor_sync(0xffffffffu, v, o);
    if (lane == 0) s[w] = v;
    __syncthreads();
    if (threadIdx.x < 32) {
        float t = (threadIdx.x < 8) ? s[threadIdx.x] : 0.f;
        #pragma unroll
        for (int o = 4; o; o >>= 1) t += __shfl_xor_sync(0xffffffffu, t, o);
        if (threadIdx.x == 0) tot = t;
    }
    __syncthreads();
    return tot;
}

// ---------------- elementwise kernels ----------------
__global__ void concat_kernel(const float* __restrict__ x, const float* __restrict__ sl,
                              const float* __restrict__ cr, float* __restrict__ out)
{
    int idx = blockIdx.x * blockDim.x + threadIdx.x;   // NTOK*512
    int c = idx & 511, r = idx >> 9;
    float v;
    if (c < STATE)      v = x[(size_t)r * STATE + c];
    else if (c == STATE) v = sl[r];
    else                 v = cr[r];
    out[idx] = v;
}

__global__ void conv_silu_kernel(const float* __restrict__ zb, const float* __restrict__ cw,
                                 const float* __restrict__ cb, float* __restrict__ out)
{
    int idx = blockIdx.x * blockDim.x + threadIdx.x;   // NTOK*CONV_DIM
    if (idx >= NTOK * CONV_DIM) return;
    int ch = idx % CONV_DIM;
    int t  = idx / CONV_DIM;
    int l = t & (SEQ - 1), b = t >> 9;
    float s = cb[ch];
    #pragma unroll
    for (int k = 0; k < DCONV; k++) {
        int ll = l - (DCONV - 1) + k;
        if (ll >= 0)
            s = fmaf(zb[((size_t)(b * SEQ + ll)) * D_IN_PROJ + D_INNER + ch], cw[ch * DCONV + k], s);
    }
    out[idx] = siluf(s);
}

__global__ void dt_kernel(const float* __restrict__ zb, const float* __restrict__ dtb,
                          const float* __restrict__ Alog,
                          float* __restrict__ dt, float* __restrict__ dA)
{
    int idx = blockIdx.x * blockDim.x + threadIdx.x;   // NTOK*NHEADS
    if (idx >= NTOK * NHEADS) return;
    int hh = idx & (NHEADS - 1), row = idx >> 5;
    float v = zb[(size_t)row * D_IN_PROJ + (D_INNER + CONV_DIM) + hh] + dtb[hh];
    float sp = (v > 20.f) ? v : log1pf(expf(v));
    float a = -expf(Alog[hh]);
    dt[idx] = sp;
    dA[idx] = expf(sp * a);
}

// ---------------- selective scan: 1 CTA per (b, head), smem-staged B/C/x ----------------
// 256 threads: p = tid>>2 (0..63), nq = tid&3. Chunks of 8 timesteps, cp.async
// double-buffered. Per-step gmem traffic drops from ~64KB to ~1.25KB per CTA.
#define SCHUNK 8
#define NCHUNK (SEQ / SCHUNK)

__global__ __launch_bounds__(256)
void scan_kernel(const float* __restrict__ conv, const float* __restrict__ dt,
                 const float* __restrict__ dA, const float* __restrict__ Dsk,
                 float* __restrict__ y)
{
    // per buffer: B[8][128], C[8][128], X[8][64] floats
    __shared__ float sB[2][SCHUNK][D_STATE];
    __shared__ float sC[2][SCHUNK][D_STATE];
    __shared__ float sX[2][SCHUNK][HEADDIM];

    int bh = blockIdx.x;
    int b = bh >> 5, hh = bh & 31;
    int tid = threadIdx.x;
    int p = tid >> 2, nq = tid & 3;

    const size_t convb = (size_t)b * SEQ * CONV_DIM;
    const uint32_t sBa = smem_to_u32(&sB[0][0][0]);
    const uint32_t sCa = smem_to_u32(&sC[0][0][0]);
    const uint32_t sXa = smem_to_u32(&sX[0][0][0]);

    auto issue = [&](int ch) {
        const int l0 = ch * SCHUNK;
        const int buf = ch & 1;
        // B + C: 512 float4s, 2 per thread
        {
            int idx = tid;                       // 0..255 -> B
            int st = idx >> 5, f4 = idx & 31;
            const float* src = conv + convb + (size_t)(l0 + st) * CONV_DIM + D_INNER + f4 * 4;
            CP_ASYNC16(sBa + (uint32_t)(buf * SCHUNK * D_STATE + st * D_STATE + f4 * 4) * 4u, src);
        }
        {
            int idx = tid;                       // 0..255 -> C
            int st = idx >> 5, f4 = idx & 31;
            const float* src = conv + convb + (size_t)(l0 + st) * CONV_DIM + D_INNER + D_STATE + f4 * 4;
            CP_ASYNC16(sCa + (uint32_t)(buf * SCHUNK * D_STATE + st * D_STATE + f4 * 4) * 4u, src);
        }
        if (tid < 128) {                         // X: 128 float4s
            int st = tid >> 4, f4 = tid & 15;
            const float* src = conv + convb + (size_t)(l0 + st) * CONV_DIM + hh * HEADDIM + f4 * 4;
            CP_ASYNC16(sXa + (uint32_t)(buf * SCHUNK * HEADDIM + st * HEADDIM + f4 * 4) * 4u, src);
        }
        CP_COMMIT();
    };

    float hs[32];
    #pragma unroll
    for (int i = 0; i < 32; i++) hs[i] = 0.f;
    float dsk = Dsk[hh];

    issue(0);

    for (int ch = 0; ch < NCHUNK; ch++) {
        if (ch + 1 < NCHUNK) { issue(ch + 1); CP_WAIT1(); }
        else                 { CP_WAIT0(); }
        __syncthreads();
        const int buf = ch & 1;

        #pragma unroll 1
        for (int s = 0; s < SCHUNK; s++) {
            int l = ch * SCHUNK + s;
            int tix = (b * SEQ + l) * NHEADS + hh;
            float dtv = dt[tix];
            float dav = dA[tix];
            float xp = sX[buf][s][p];
            float coef = dtv * xp;
            const float4* B4 = (const float4*)&sB[buf][s][nq * 32];
            const float4* C4 = (const float4*)&sC[buf][s][nq * 32];
            float acc = 0.f;
            #pragma unroll
            for (int i = 0; i < 8; i++) {
                float4 bv = B4[i];
                float4 cv = C4[i];
                int j = i * 4;
                hs[j    ] = fmaf(hs[j    ], dav, coef * bv.x); acc = fmaf(hs[j    ], cv.x, acc);
                hs[j + 1] = fmaf(hs[j + 1], dav, coef * bv.y); acc = fmaf(hs[j + 1], cv.y, acc);
                hs[j + 2] = fmaf(hs[j + 2], dav, coef * bv.z); acc = fmaf(hs[j + 2], cv.z, acc);
                hs[j + 3] = fmaf(hs[j + 3], dav, coef * bv.w); acc = fmaf(hs[j + 3], cv.w, acc);
            }
            acc += __shfl_xor_sync(0xffffffffu, acc, 1);
            acc += __shfl_xor_sync(0xffffffffu, acc, 2);
            if (nq == 0)
                y[((size_t)(b * SEQ + l)) * D_INNER + hh * HEADDIM + p] = acc + dsk * xp;
        }
        __syncthreads();
    }
}

// ---------------- gated RMSNorm ----------------
__global__ __launch_bounds__(256)
void gated_norm_kernel(const float* __restrict__ y, const float* __restrict__ z,
                       const float* __restrict__ nw, float* __restrict__ out)
{
    int r = blockIdx.x;
    float g[8];
    float ss = 0.f;
    #pragma unroll
    for (int j = 0; j < 8; j++) {
        int c = j * 256 + threadIdx.x;
        float zv = z[(size_t)r * D_IN_PROJ + c];
        float gv = y[(size_t)r * D_INNER + c] * siluf(zv);
        g[j] = gv;
        ss = fmaf(gv, gv, ss);
    }
    ss = blockReduceSum256(ss);
    float inv = rsqrtf(ss / (float)D_INNER + 1e-5f);
    #pragma unroll
    for (int j = 0; j < 8; j++) {
        int c = j * 256 + threadIdx.x;
        out[(size_t)r * D_INNER + c] = g[j] * inv * nw[c];
    }
}

// ---------------- final N=1 projection ----------------
__global__ __launch_bounds__(256)
void dot_kernel(const float* __restrict__ t, const float* __restrict__ w,
                const float* __restrict__ b, float* __restrict__ out)
{
    int r = blockIdx.x;
    float s = 0.f;
    for (int k = threadIdx.x; k < D_MODEL; k += 256)
        s = fmaf(t[(size_t)r * D_MODEL + k], w[k], s);
    s = blockReduceSum256(s);
    if (threadIdx.x == 0) out[r] = s + b[0];
}

// ---------------- launch ----------------
extern "C" void kernel_launch(void* const* d_in, const int* in_sizes, int n_in,
                              void* d_out, int out_size)
{
    const float* x    = (const float*)d_in[0];
    const float* sl   = (const float*)d_in[1];
    const float* cr   = (const float*)d_in[2];
    const float* iw1  = (const float*)d_in[3];
    const float* ib1  = (const float*)d_in[4];
    const float* iw2  = (const float*)d_in[5];
    const float* ib2  = (const float*)d_in[6];
    const float* Win  = (const float*)d_in[7];
    const float* cw   = (const float*)d_in[8];
    const float* cb   = (const float*)d_in[9];
    const float* dtb  = (const float*)d_in[10];
    const float* Alog = (const float*)d_in[11];
    const float* Dsk  = (const float*)d_in[12];
    const float* nw   = (const float*)d_in[13];
    const float* Wout = (const float*)d_in[14];
    const float* ow1  = (const float*)d_in[15];
    const float* ob1  = (const float*)d_in[16];
    const float* ow2  = (const float*)d_in[17];
    const float* ob2  = (const float*)d_in[18];
    float* out = (float*)d_out;

    float *cat, *tmp, *h, *z, *conv, *dt, *dA, *y, *yn;
    cudaGetSymbolAddress((void**)&cat,  g_cat);
    cudaGetSymbolAddress((void**)&tmp,  g_tmp);
    cudaGetSymbolAddress((void**)&h,    g_h);
    cudaGetSymbolAddress((void**)&z,    g_z);
    cudaGetSymbolAddress((void**)&conv, g_conv);
    cudaGetSymbolAddress((void**)&dt,   g_dt);
    cudaGetSymbolAddress((void**)&dA,   g_dA);
    cudaGetSymbolAddress((void**)&y,    g_y);
    cudaGetSymbolAddress((void**)&yn,   g_yn);

    cudaFuncSetAttribute(mma_gemm<1,1>, cudaFuncAttributeMaxDynamicSharedMemorySize, GEMM_SMEM_BYTES);
    cudaFuncSetAttribute(mma_gemm<1,0>, cudaFuncAttributeMaxDynamicSharedMemorySize, GEMM_SMEM_BYTES);
    cudaFuncSetAttribute(mma_gemm<0,0>, cudaFuncAttributeMaxDynamicSharedMemorySize, GEMM_SMEM_BYTES);

    const int MT = NTOK / 128;   // 16 M-tiles

    // input MLP
    concat_kernel<<<NTOK * 512 / 256, 256>>>(x, sl, cr, cat);
    mma_gemm<1,1><<<dim3(512/128, MT), 256, GEMM_SMEM_BYTES>>>(cat, iw1, ib1, tmp, NTOK, 512, 512);
    mma_gemm<1,0><<<dim3(D_MODEL/128, MT), 256, GEMM_SMEM_BYTES>>>(tmp, iw2, ib2, h, NTOK, D_MODEL, 512);

    for (int i = 0; i < NBLOCKS; i++) {
        mma_gemm<0,0><<<dim3((D_IN_PROJ + 127)/128, MT), 256, GEMM_SMEM_BYTES>>>(
            h, Win + (size_t)i * D_MODEL * D_IN_PROJ, nullptr, z, NTOK, D_IN_PROJ, D_MODEL);
        conv_silu_kernel<<<(NTOK * CONV_DIM + 255) / 256, 256>>>(
            z, cw + (size_t)i * CONV_DIM * DCONV, cb + (size_t)i * CONV_DIM, conv);
        dt_kernel<<<(NTOK * NHEADS) / 256, 256>>>(
            z, dtb + i * NHEADS, Alog + i * NHEADS, dt, dA);
        scan_kernel<<<BATCH * NHEADS, 256>>>(conv, dt, dA, Dsk + i * NHEADS, y);
        gated_norm_kernel<<<NTOK, 256>>>(y, z, nw + (size_t)i * D_INNER, yn);
        mma_gemm<0,0><<<dim3(D_MODEL/128, MT), 256, GEMM_SMEM_BYTES>>>(
            yn, Wout + (size_t)i * D_INNER * D_MODEL, nullptr, h, NTOK, D_MODEL, D_INNER);
    }

    // output MLP
    mma_gemm<1,1><<<dim3(D_MODEL/128, MT), 256, GEMM_SMEM_BYTES>>>(h, ow1, ob1, tmp, NTOK, D_MODEL, D_MODEL);
    dot_kernel<<<NTOK, 256>>>(tmp, ow2, ob2, out);
}

// round 8
// speedup vs baseline: 1.6930x; 1.1481x over previous
#include <cuda_runtime.h>
#include <cuda.h>
#include <cuda_bf16.h>
#include <math.h>
#include <stdint.h>

// ---------------- problem constants ----------------
#define BATCH     4
#define SEQ       512
#define NTOK      (BATCH*SEQ)          // 2048
#define STATE     510
#define D_MODEL   1024
#define D_INNER   2048
#define D_STATE   128
#define NHEADS    32
#define HEADDIM   64
#define DCONV     4
#define CONV_DIM  (D_INNER + 2*D_STATE)            // 2304
#define D_IN_PROJ (2*D_INNER + 2*D_STATE + NHEADS) // 4384
#define NBLOCKS   4

// ---------------- scratch (device globals, no allocs) ----------------
__device__ float g_cat [NTOK * 512];
__device__ float g_tmp [NTOK * D_MODEL];
__device__ float g_h   [NTOK * D_MODEL];
__device__ float g_z   [NTOK * D_IN_PROJ];
__device__ float g_conv[NTOK * CONV_DIM];
__device__ float g_dt  [NTOK * NHEADS];
__device__ float g_dA  [NTOK * NHEADS];
__device__ float g_y   [NTOK * D_INNER];
__device__ float g_yn  [NTOK * D_INNER];

// ================= helpers =================
__device__ __forceinline__ uint32_t smem_to_u32(const void* p) {
    uint32_t a;
    asm("{ .reg .u64 t; cvta.to.shared.u64 t, %1; cvt.u32.u64 %0, t; }" : "=r"(a) : "l"(p));
    return a;
}
#define CP_ASYNC16(dst, src) \
    asm volatile("cp.async.ca.shared.global [%0], [%1], 16;" :: "r"(dst), "l"(src) : "memory")
#define CP_ASYNC4(dst, src) \
    asm volatile("cp.async.ca.shared.global [%0], [%1], 4;" :: "r"(dst), "l"(src) : "memory")
#define CP_COMMIT() asm volatile("cp.async.commit_group;" ::: "memory")
#define CP_WAIT1()  asm volatile("cp.async.wait_group 1;" ::: "memory")
#define CP_WAIT0()  asm volatile("cp.async.wait_group 0;" ::: "memory")

// Split x0,x1 into packed bf16x2 hi and lo parts (hi half of reg = x1).
__device__ __forceinline__ void bf16x2split(float x0, float x1, uint32_t& hi, uint32_t& lo) {
    uint32_t h;
    asm("cvt.rn.bf16x2.f32 %0, %1, %2;" : "=r"(h) : "f"(x1), "f"(x0));
    float h0 = __uint_as_float(h << 16);
    float h1 = __uint_as_float(h & 0xffff0000u);
    float l0 = x0 - h0;
    float l1 = x1 - h1;
    hi = h;
    asm("cvt.rn.bf16x2.f32 %0, %1, %2;" : "=r"(lo) : "f"(l1), "f"(l0));
}

#define MMA_BF16(cr, a, b) \
    asm volatile("mma.sync.aligned.m16n8k16.row.col.f32.bf16.bf16.f32 " \
        "{%0,%1,%2,%3},{%4,%5,%6,%7},{%8,%9},{%0,%1,%2,%3};" \
        : "+f"((cr)[0]), "+f"((cr)[1]), "+f"((cr)[2]), "+f"((cr)[3]) \
        : "r"((a)[0]), "r"((a)[1]), "r"((a)[2]), "r"((a)[3]), \
          "r"((b)[0]), "r"((b)[1]))

// ================= bf16x3 tensor-core GEMM (compensated) =================
// C[M,N] = A[M,K] @ B[K,N] (+bias)(relu). CTA tile 128x128, K-chunk 32,
// cp.async double-buffered float smem; bf16 hi/lo split at frag-load time.
// 8 warps, warp tile 64x32, m16n8k16 atoms, 3 compensation terms.
#define GEMM_SMEM_FLOATS (2 * 8960)
#define GEMM_SMEM_BYTES  (GEMM_SMEM_FLOATS * 4)

template<int BIAS, int RELU>
__global__ __launch_bounds__(256)
void mma_gemm(const float* __restrict__ A, const float* __restrict__ B,
              const float* __restrict__ bias, float* __restrict__ C,
              int M, int N, int K)
{
    extern __shared__ float sm[];
    const uint32_t sbase = smem_to_u32(sm);

    const int tid = threadIdx.x, lane = tid & 31, w = tid >> 5;
    const int wm = w >> 2, wn = w & 3;          // warp grid 2(m) x 4(n)
    const int grp = lane >> 2, kq = lane & 3;
    const int m0 = blockIdx.y * 128, n0 = blockIdx.x * 128;

    const int ar = tid >> 1, ah = tid & 1;      // A: row, k-half
    const int bk = tid >> 3, bf = tid & 7;      // B: k-row, f4 subgroup

    float c[4][4][4];
    #pragma unroll
    for (int i = 0; i < 4; i++)
        #pragma unroll
        for (int j = 0; j < 4; j++)
            #pragma unroll
            for (int q = 0; q < 4; q++) c[i][j][q] = 0.f;

    const int nch = K >> 5;

    auto issue = [&](int ch) {
        const uint32_t boff = (uint32_t)(ch & 1) * (8960u * 4u);
        const int k0 = ch << 5;
        const float* asrc = A + (size_t)(m0 + ar) * K + k0 + ah * 16;
        uint32_t adst = sbase + boff + (uint32_t)(ar * 36 + ah * 16) * 4u;
        #pragma unroll
        for (int i = 0; i < 4; i++)
            CP_ASYNC16(adst + i * 16u, asrc + i * 4);
        #pragma unroll
        for (int i = 0; i < 4; i++) {
            int nf = bf + i * 8;
            int ncol = n0 + nf * 4;
            const float* bsrc = B + (size_t)(k0 + bk) * N + (ncol < N ? ncol : 0);
            uint32_t bdst = sbase + boff + (4608u + (uint32_t)(bk * 136 + nf * 4)) * 4u;
            CP_ASYNC16(bdst, bsrc);
        }
        CP_COMMIT();
    };

    issue(0);

    for (int ch = 0; ch < nch; ch++) {
        if (ch + 1 < nch) { issue(ch + 1); CP_WAIT1(); }
        else              { CP_WAIT0(); }
        __syncthreads();

        const float* Af = sm + (ch & 1) * 8960;
        const float* Bf = Af + 4608;

        #pragma unroll
        for (int ks = 0; ks < 2; ks++) {
            const int kb = ks * 16;
            uint32_t ahi[4][4], alo[4][4];
            #pragma unroll
            for (int ma = 0; ma < 4; ma++) {
                int r0 = wm * 64 + ma * 16 + grp;
                const float* a0p = &Af[r0 * 36 + kb + 2 * kq];
                const float* a1p = &Af[(r0 + 8) * 36 + kb + 2 * kq];
                float2 v00 = *(const float2*)a0p;         // k = 2kq, 2kq+1
                float2 v10 = *(const float2*)a1p;
                float2 v01 = *(const float2*)(a0p + 8);   // k + 8
                float2 v11 = *(const float2*)(a1p + 8);
                bf16x2split(v00.x, v00.y, ahi[ma][0], alo[ma][0]);
                bf16x2split(v10.x, v10.y, ahi[ma][1], alo[ma][1]);
                bf16x2split(v01.x, v01.y, ahi[ma][2], alo[ma][2]);
                bf16x2split(v11.x, v11.y, ahi[ma][3], alo[ma][3]);
            }
            uint32_t bhi[4][2], blo[4][2];
            #pragma unroll
            for (int na = 0; na < 4; na++) {
                int col = wn * 32 + na * 8 + grp;
                float y00 = Bf[(kb + 2 * kq) * 136 + col];
                float y01 = Bf[(kb + 2 * kq + 1) * 136 + col];
                float y10 = Bf[(kb + 2 * kq + 8) * 136 + col];
                float y11 = Bf[(kb + 2 * kq + 9) * 136 + col];
                bf16x2split(y00, y01, bhi[na][0], blo[na][0]);
                bf16x2split(y10, y11, bhi[na][1], blo[na][1]);
            }
            #pragma unroll
            for (int ma = 0; ma < 4; ma++)
                #pragma unroll
                for (int na = 0; na < 4; na++) {
                    MMA_BF16(c[ma][na], ahi[ma], bhi[na]);
                    MMA_BF16(c[ma][na], ahi[ma], blo[na]);
                    MMA_BF16(c[ma][na], alo[ma], bhi[na]);
                }
        }
        __syncthreads();
    }

    #pragma unroll
    for (int ma = 0; ma < 4; ma++) {
        int row = m0 + wm * 64 + ma * 16 + grp;
        #pragma unroll
        for (int na = 0; na < 4; na++) {
            int col = n0 + wn * 32 + na * 8 + kq * 2;
            if (col < N) {
                float b0 = 0.f, b1 = 0.f;
                if (BIAS) { b0 = bias[col]; b1 = bias[col + 1]; }
                float v0 = c[ma][na][0] + b0, v1 = c[ma][na][1] + b1;
                float v2 = c[ma][na][2] + b0, v3 = c[ma][na][3] + b1;
                if (RELU) {
                    v0 = fmaxf(v0, 0.f); v1 = fmaxf(v1, 0.f);
                    v2 = fmaxf(v2, 0.f); v3 = fmaxf(v3, 0.f);
                }
                *(float2*)(C + (size_t)row * N + col)       = make_float2(v0, v1);
                *(float2*)(C + (size_t)(row + 8) * N + col) = make_float2(v2, v3);
            }
        }
    }
}

// ---------------- helpers ----------------
__device__ __forceinline__ float siluf(float v) { return v / (1.f + expf(-v)); }

__device__ __forceinline__ float blockReduceSum256(float v) {
    __shared__ float s[8];
    __shared__ float tot;
    int lane = threadIdx.x & 31, w = threadIdx.x >> 5;
    #pragma unroll
    for (int o = 16; o; o >>= 1) v += __shfl_xor_sync(0xffffffffu, v, o);
    if (lane == 0) s[w] = v;
    __syncthreads();
    if (threadIdx.x < 32) {
        float t = (threadIdx.x < 8) ? s[threadIdx.x] : 0.f;
        #pragma unroll
        for (int o = 4; o; o >>= 1) t += __shfl_xor_sync(0xffffffffu, t, o);
        if (threadIdx.x == 0) tot = t;
    }
    __syncthreads();
    return tot;
}

// ---------------- elementwise kernels ----------------
__global__ void concat_kernel(const float* __restrict__ x, const float* __restrict__ sl,
                              const float* __restrict__ cr, float* __restrict__ out)
{
    int idx = blockIdx.x * blockDim.x + threadIdx.x;   // NTOK*512
    int c = idx & 511, r = idx >> 9;
    float v;
    if (c < STATE)      v = x[(size_t)r * STATE + c];
    else if (c == STATE) v = sl[r];
    else                 v = cr[r];
    out[idx] = v;
}

__global__ void conv_silu_kernel(const float* __restrict__ zb, const float* __restrict__ cw,
                                 const float* __restrict__ cb, float* __restrict__ out)
{
    int idx = blockIdx.x * blockDim.x + threadIdx.x;   // NTOK*CONV_DIM
    if (idx >= NTOK * CONV_DIM) return;
    int ch = idx % CONV_DIM;
    int t  = idx / CONV_DIM;
    int l = t & (SEQ - 1), b = t >> 9;
    float s = cb[ch];
    #pragma unroll
    for (int k = 0; k < DCONV; k++) {
        int ll = l - (DCONV - 1) + k;
        if (ll >= 0)
            s = fmaf(zb[((size_t)(b * SEQ + ll)) * D_IN_PROJ + D_INNER + ch], cw[ch * DCONV + k], s);
    }
    out[idx] = siluf(s);
}

__global__ void dt_kernel(const float* __restrict__ zb, const float* __restrict__ dtb,
                          const float* __restrict__ Alog,
                          float* __restrict__ dt, float* __restrict__ dA)
{
    int idx = blockIdx.x * blockDim.x + threadIdx.x;   // NTOK*NHEADS
    if (idx >= NTOK * NHEADS) return;
    int hh = idx & (NHEADS - 1), row = idx >> 5;
    float v = zb[(size_t)row * D_IN_PROJ + (D_INNER + CONV_DIM) + hh] + dtb[hh];
    float sp = (v > 20.f) ? v : log1pf(expf(v));
    float a = -expf(Alog[hh]);
    dt[idx] = sp;
    dA[idx] = expf(sp * a);
}

// ---------------- selective scan: 1 CTA per (b, head), smem-staged ----------------
#define SCHUNK 8
#define NCHUNK (SEQ / SCHUNK)

__global__ __launch_bounds__(256)
void scan_kernel(const float* __restrict__ conv, const float* __restrict__ dt,
                 const float* __restrict__ dA, const float* __restrict__ Dsk,
                 float* __restrict__ y)
{
    __shared__ float sB[2][SCHUNK][D_STATE];
    __shared__ float sC[2][SCHUNK][D_STATE];
    __shared__ float sX[2][SCHUNK][HEADDIM];
    __shared__ float sdt[2][SCHUNK];
    __shared__ float sda[2][SCHUNK];

    int bh = blockIdx.x;
    int b = bh >> 5, hh = bh & 31;
    int tid = threadIdx.x;
    int p = tid >> 2, nq = tid & 3;

    const size_t convb = (size_t)b * SEQ * CONV_DIM;
    const uint32_t sBa = smem_to_u32(&sB[0][0][0]);
    const uint32_t sCa = smem_to_u32(&sC[0][0][0]);
    const uint32_t sXa = smem_to_u32(&sX[0][0][0]);
    const uint32_t sdta = smem_to_u32(&sdt[0][0]);
    const uint32_t sdaa = smem_to_u32(&sda[0][0]);

    auto issue = [&](int ch) {
        const int l0 = ch * SCHUNK;
        const int buf = ch & 1;
        {
            int st = tid >> 5, f4 = tid & 31;
            const float* src = conv + convb + (size_t)(l0 + st) * CONV_DIM + D_INNER + f4 * 4;
            CP_ASYNC16(sBa + (uint32_t)(buf * SCHUNK * D_STATE + st * D_STATE + f4 * 4) * 4u, src);
        }
        {
            int st = tid >> 5, f4 = tid & 31;
            const float* src = conv + convb + (size_t)(l0 + st) * CONV_DIM + D_INNER + D_STATE + f4 * 4;
            CP_ASYNC16(sCa + (uint32_t)(buf * SCHUNK * D_STATE + st * D_STATE + f4 * 4) * 4u, src);
        }
        if (tid < 128) {
            int st = tid >> 4, f4 = tid & 15;
            const float* src = conv + convb + (size_t)(l0 + st) * CONV_DIM + hh * HEADDIM + f4 * 4;
            CP_ASYNC16(sXa + (uint32_t)(buf * SCHUNK * HEADDIM + st * HEADDIM + f4 * 4) * 4u, src);
        } else if (tid < 136) {
            int s = tid - 128;
            CP_ASYNC4(sdta + (uint32_t)(buf * SCHUNK + s) * 4u,
                      dt + (size_t)(b * SEQ + l0 + s) * NHEADS + hh);
        } else if (tid < 144) {
            int s = tid - 136;
            CP_ASYNC4(sdaa + (uint32_t)(buf * SCHUNK + s) * 4u,
                      dA + (size_t)(b * SEQ + l0 + s) * NHEADS + hh);
        }
        CP_COMMIT();
    };

    float hs[32];
    #pragma unroll
    for (int i = 0; i < 32; i++) hs[i] = 0.f;
    float dsk = Dsk[hh];

    issue(0);

    for (int ch = 0; ch < NCHUNK; ch++) {
        if (ch + 1 < NCHUNK) { issue(ch + 1); CP_WAIT1(); }
        else                 { CP_WAIT0(); }
        __syncthreads();
        const int buf = ch & 1;

        #pragma unroll 1
        for (int s = 0; s < SCHUNK; s++) {
            int l = ch * SCHUNK + s;
            float dtv = sdt[buf][s];
            float dav = sda[buf][s];
            float xp = sX[buf][s][p];
            float coef = dtv * xp;
            const float4* B4 = (const float4*)&sB[buf][s][nq * 32];
            const float4* C4 = (const float4*)&sC[buf][s][nq * 32];
            float acc = 0.f;
            #pragma unroll
            for (int i = 0; i < 8; i++) {
                float4 bv = B4[i];
                float4 cv = C4[i];
                int j = i * 4;
                hs[j    ] = fmaf(hs[j    ], dav, coef * bv.x); acc = fmaf(hs[j    ], cv.x, acc);
                hs[j + 1] = fmaf(hs[j + 1], dav, coef * bv.y); acc = fmaf(hs[j + 1], cv.y, acc);
                hs[j + 2] = fmaf(hs[j + 2], dav, coef * bv.z); acc = fmaf(hs[j + 2], cv.z, acc);
                hs[j + 3] = fmaf(hs[j + 3], dav, coef * bv.w); acc = fmaf(hs[j + 3], cv.w, acc);
            }
            acc += __shfl_xor_sync(0xffffffffu, acc, 1);
            acc += __shfl_xor_sync(0xffffffffu, acc, 2);
            if (nq == 0)
                y[((size_t)(b * SEQ + l)) * D_INNER + hh * HEADDIM + p] = acc + dsk * xp;
        }
        __syncthreads();
    }
}

// ---------------- gated RMSNorm ----------------
__global__ __launch_bounds__(256)
void gated_norm_kernel(const float* __restrict__ y, const float* __restrict__ z,
                       const float* __restrict__ nw, float* __restrict__ out)
{
    int r = blockIdx.x;
    float g[8];
    float ss = 0.f;
    #pragma unroll
    for (int j = 0; j < 8; j++) {
        int c = j * 256 + threadIdx.x;
        float zv = z[(size_t)r * D_IN_PROJ + c];
        float gv = y[(size_t)r * D_INNER + c] * siluf(zv);
        g[j] = gv;
        ss = fmaf(gv, gv, ss);
    }
    ss = blockReduceSum256(ss);
    float inv = rsqrtf(ss / (float)D_INNER + 1e-5f);
    #pragma unroll
    for (int j = 0; j < 8; j++) {
        int c = j * 256 + threadIdx.x;
        out[(size_t)r * D_INNER + c] = g[j] * inv * nw[c];
    }
}

// ---------------- final N=1 projection ----------------
__global__ __launch_bounds__(256)
void dot_kernel(const float* __restrict__ t, const float* __restrict__ w,
                const float* __restrict__ b, float* __restrict__ out)
{
    int r = blockIdx.x;
    float s = 0.f;
    for (int k = threadIdx.x; k < D_MODEL; k += 256)
        s = fmaf(t[(size_t)r * D_MODEL + k], w[k], s);
    s = blockReduceSum256(s);
    if (threadIdx.x == 0) out[r] = s + b[0];
}

// ---------------- launch ----------------
extern "C" void kernel_launch(void* const* d_in, const int* in_sizes, int n_in,
                              void* d_out, int out_size)
{
    const float* x    = (const float*)d_in[0];
    const float* sl   = (const float*)d_in[1];
    const float* cr   = (const float*)d_in[2];
    const float* iw1  = (const float*)d_in[3];
    const float* ib1  = (const float*)d_in[4];
    const float* iw2  = (const float*)d_in[5];
    const float* ib2  = (const float*)d_in[6];
    const float* Win  = (const float*)d_in[7];
    const float* cw   = (const float*)d_in[8];
    const float* cb   = (const float*)d_in[9];
    const float* dtb  = (const float*)d_in[10];
    const float* Alog = (const float*)d_in[11];
    const float* Dsk  = (const float*)d_in[12];
    const float* nw   = (const float*)d_in[13];
    const float* Wout = (const float*)d_in[14];
    const float* ow1  = (const float*)d_in[15];
    const float* ob1  = (const float*)d_in[16];
    const float* ow2  = (const float*)d_in[17];
    const float* ob2  = (const float*)d_in[18];
    float* out = (float*)d_out;

    float *cat, *tmp, *h, *z, *conv, *dt, *dA, *y, *yn;
    cudaGetSymbolAddress((void**)&cat,  g_cat);
    cudaGetSymbolAddress((void**)&tmp,  g_tmp);
    cudaGetSymbolAddress((void**)&h,    g_h);
    cudaGetSymbolAddress((void**)&z,    g_z);
    cudaGetSymbolAddress((void**)&conv, g_conv);
    cudaGetSymbolAddress((void**)&dt,   g_dt);
    cudaGetSymbolAddress((void**)&dA,   g_dA);
    cudaGetSymbolAddress((void**)&y,    g_y);
    cudaGetSymbolAddress((void**)&yn,   g_yn);

    cudaFuncSetAttribute(mma_gemm<1,1>, cudaFuncAttributeMaxDynamicSharedMemorySize, GEMM_SMEM_BYTES);
    cudaFuncSetAttribute(mma_gemm<1,0>, cudaFuncAttributeMaxDynamicSharedMemorySize, GEMM_SMEM_BYTES);
    cudaFuncSetAttribute(mma_gemm<0,0>, cudaFuncAttributeMaxDynamicSharedMemorySize, GEMM_SMEM_BYTES);

    const int MT = NTOK / 128;   // 16 M-tiles

    // input MLP
    concat_kernel<<<NTOK * 512 / 256, 256>>>(x, sl, cr, cat);
    mma_gemm<1,1><<<dim3(512/128, MT), 256, GEMM_SMEM_BYTES>>>(cat, iw1, ib1, tmp, NTOK, 512, 512);
    mma_gemm<1,0><<<dim3(D_MODEL/128, MT), 256, GEMM_SMEM_BYTES>>>(tmp, iw2, ib2, h, NTOK, D_MODEL, 512);

    for (int i = 0; i < NBLOCKS; i++) {
        mma_gemm<0,0><<<dim3((D_IN_PROJ + 127)/128, MT), 256, GEMM_SMEM_BYTES>>>(
            h, Win + (size_t)i * D_MODEL * D_IN_PROJ, nullptr, z, NTOK, D_IN_PROJ, D_MODEL);
        conv_silu_kernel<<<(NTOK * CONV_DIM + 255) / 256, 256>>>(
            z, cw + (size_t)i * CONV_DIM * DCONV, cb + (size_t)i * CONV_DIM, conv);
        dt_kernel<<<(NTOK * NHEADS) / 256, 256>>>(
            z, dtb + i * NHEADS, Alog + i * NHEADS, dt, dA);
        scan_kernel<<<BATCH * NHEADS, 256>>>(conv, dt, dA, Dsk + i * NHEADS, y);
        gated_norm_kernel<<<NTOK, 256>>>(y, z, nw + (size_t)i * D_INNER, yn);
        mma_gemm<0,0><<<dim3(D_MODEL/128, MT), 256, GEMM_SMEM_BYTES>>>(
            yn, Wout + (size_t)i * D_INNER * D_MODEL, nullptr, h, NTOK, D_MODEL, D_INNER);
    }

    // output MLP
    mma_gemm<1,1><<<dim3(D_MODEL/128, MT), 256, GEMM_SMEM_BYTES>>>(h, ow1, ob1, tmp, NTOK, D_MODEL, D_MODEL);
    dot_kernel<<<NTOK, 256>>>(tmp, ow2, ob2, out);
}